// round 10
// baseline (speedup 1.0000x reference)
#include <cuda_runtime.h>
#include <cstdint>
#include <math.h>

// Kendall's tau loss via discordant-pair count (no ties in random normals):
//   loss = 4*D / (n(n-1)),  D = #{i<j : sign(p_i-p_j) != sign(t_i-t_j)}
// R10: TILE=128 / NTH=128 / 1 row/thread -> 2080 blocks = 14.05/SM (balanced,
// vs 528 = 3.57/SM whose 4-vs-3 imbalance set the critical path), ~56 warps/SM.
// Cheap fp32-sqrt + int-fixup triangular decode (R5's fp64 decode was its
// regression). Inner loop: fused FADD2+xor asm, dual-pipe accumulate.

#define TILE 128
#define NTH 128

__device__ unsigned long long g_cnt = 0;  // bits[0:40) count, bits[40:) block ctr

__device__ __forceinline__ unsigned long long pack2(float lo, float hi) {
    unsigned long long r;
    asm("mov.b64 %0, {%1, %2};" : "=l"(r) : "f"(lo), "f"(hi));
    return r;
}

// xor of the two fp32 halves of (a + nb), single asm block.
__device__ __forceinline__ unsigned int xor_word(unsigned long long a,
                                                 unsigned long long nb) {
    unsigned int r;
    asm("{\n\t"
        ".reg .b64 s;\n\t"
        ".reg .b32 lo, hi;\n\t"
        "add.rn.f32x2 s, %1, %2;\n\t"
        "mov.b64 {lo, hi}, s;\n\t"
        "xor.b32 %0, lo, hi;\n\t"
        "}" : "=r"(r) : "l"(a), "l"(nb));
    return r;
}

// alu-pipe accumulate: LEA.HI (c += bit31)
__device__ __forceinline__ void acc_alu(unsigned int& c, unsigned long long a,
                                        unsigned long long nb) {
    c += xor_word(a, nb) >> 31;
}
// fma-pipe accumulate: IMAD.HI.U32, multiplier ==2 but runtime-opaque
__device__ __forceinline__ void acc_fma(unsigned int& c, unsigned long long a,
                                        unsigned long long nb,
                                        unsigned int two) {
    unsigned int x = xor_word(a, nb);
    asm("mad.hi.u32 %0, %1, %2, %0;" : "+r"(c) : "r"(x), "r"(two));
}

__device__ __forceinline__ int row_start(int r, int ntiles) {
    return r * ntiles - (r * (r - 1)) / 2;
}

__global__ __launch_bounds__(NTH) void kt_kernel(
    const float* __restrict__ p, const float* __restrict__ t,
    float* __restrict__ out, int n)
{
    const int ntiles = (n + TILE - 1) / TILE;
    const unsigned int two = (unsigned int)blockDim.x >> 6;  // ==2, opaque

    // Triangular decode via fp32 sqrt (MUFU) + integer fixup.
    const int b = blockIdx.x;
    const float m = 2.0f * (float)ntiles + 1.0f;
    int bi = (int)((m - sqrtf(m * m - 8.0f * (float)b)) * 0.5f);
    if (bi > 0 && row_start(bi, ntiles) > b) --bi;
    while (row_start(bi + 1, ntiles) <= b) ++bi;
    const int bj = bi + (b - row_start(bi, ntiles));

    __shared__ __align__(16) float2 snb[TILE];  // (-p_j, -t_j)

    const int tid = threadIdx.x;
    const int jb = bj * TILE;
    const int jlim = min(TILE, n - jb);

    if (tid < jlim) snb[tid] = make_float2(-p[jb + tid], -t[jb + tid]);
    __syncthreads();

    const int ib = bi * TILE;
    unsigned int c0 = 0, c1 = 0;

    const bool full = (jlim == TILE) && (ib + TILE <= n);

    if (full && bi != bj) {
        // Full off-diagonal tile: all (i, j) valid. One row per thread.
        const unsigned long long a = pack2(p[ib + tid], t[ib + tid]);
        const ulonglong2* B2 = reinterpret_cast<const ulonglong2*>(snb);
        #pragma unroll 8
        for (int k2 = 0; k2 < TILE / 2; ++k2) {
            const ulonglong2 bb = B2[k2];   // LDS.128: two j's
            acc_alu(c0, a, bb.x);           // even j -> alu pipe
            acc_fma(c1, a, bb.y, two);      // odd j  -> fma pipe
        }
    } else if (full) {
        // Diagonal tile: local j > local i.
        const unsigned long long* B =
            reinterpret_cast<const unsigned long long*>(snb);
        const unsigned long long a = pack2(p[ib + tid], t[ib + tid]);
        int k = tid + 1;
        for (; k + 1 < TILE; k += 2) {
            acc_alu(c0, a, B[k]);
            acc_fma(c1, a, B[k + 1], two);
        }
        if (k < TILE) acc_alu(c0, a, B[k]);
    } else {
        // Partial tile (not hit for n=8192; kept for generality).
        const unsigned long long* B =
            reinterpret_cast<const unsigned long long*>(snb);
        const int i = ib + tid;
        if (i < n) {
            const unsigned long long a = pack2(p[i], t[i]);
            for (int k = 0; k < jlim; ++k)
                if (jb + k > i) acc_alu(c0, a, B[k]);
        }
    }

    // Warp reduction: single REDUX.SUM.
    unsigned int cnt = __reduce_add_sync(0xFFFFFFFFu, c0 + c1);

    __shared__ unsigned int wsum[NTH / 32];
    if ((tid & 31) == 0) wsum[tid >> 5] = cnt;
    __syncthreads();

    if (tid == 0) {
        unsigned int total = 0;
        #pragma unroll
        for (int w = 0; w < NTH / 32; ++w) total += wsum[w];

        // One atomic: low 40 bits accumulate D, high bits count finished
        // blocks; the same atomic carries both, so no fence is needed.
        const unsigned long long pkt =
            (unsigned long long)total | (1ULL << 40);
        const unsigned long long old = atomicAdd(&g_cnt, pkt);
        if ((old >> 40) == (unsigned long long)(gridDim.x - 1)) {
            const unsigned long long D = (old + pkt) & ((1ULL << 40) - 1ULL);
            const double nn = (double)n;
            out[0] = (float)(4.0 * (double)D / (nn * (nn - 1.0)));
            atomicExch(&g_cnt, 0ULL);   // reset for next graph replay
        }
    }
}

extern "C" void kernel_launch(void* const* d_in, const int* in_sizes, int n_in,
                              void* d_out, int out_size)
{
    const float* predictions = (const float*)d_in[0];
    const float* true_labels = (const float*)d_in[1];
    float* out = (float*)d_out;
    const int n = in_sizes[0];

    const int ntiles = (n + TILE - 1) / TILE;
    const int nblocks = ntiles * (ntiles + 1) / 2;

    kt_kernel<<<nblocks, NTH>>>(predictions, true_labels, out, n);
}

// round 11
// speedup vs baseline: 1.6813x; 1.6813x over previous
#include <cuda_runtime.h>
#include <cstdint>

// Kendall's tau loss via discordant-pair count (no ties in random normals):
//   loss = 4*D / (n(n-1)),  D = #{i<j : (p_i<p_j) != (t_i<t_j)}
// R11: 3-instruction pair test -- FSETP.LT + FSETP.LT.XOR (bool-combine) +
// predicated IADD. Kills the 2-MOV/pair tax of the packed-f32x2 formulation
// (every prior round measured ~6.5M issued slots vs ~3.5M modeled; this one
// models ~3.6M). Shape: proven 528 blocks x 128 threads, 2 rows/thread.

#define TILE 256
#define NTH 128

__device__ unsigned long long g_cnt = 0;  // bits[0:40) count, bits[40:) block ctr

// c += (pi < pj) XOR (ti < tj)   -- FSETP, FSETP.XOR, @P IADD (3 slots)
__device__ __forceinline__ void acc_pair(unsigned int& c,
                                         float pi, float ti,
                                         float pj, float tj) {
    asm("{\n\t"
        ".reg .pred q0, q1;\n\t"
        "setp.lt.f32 q0, %1, %2;\n\t"
        "setp.lt.xor.f32 q1, %3, %4, q0;\n\t"
        "@q1 add.u32 %0, %0, 1;\n\t"
        "}" : "+r"(c) : "f"(pi), "f"(pj), "f"(ti), "f"(tj));
}

__global__ __launch_bounds__(NTH) void kt_kernel(
    const float* __restrict__ p, const float* __restrict__ t,
    float* __restrict__ out, int n)
{
    const int ntiles = (n + TILE - 1) / TILE;

    // Linear block id -> upper-triangular (bi, bj), bj >= bi.
    int b = blockIdx.x;
    int bi = 0;
    while (b >= ntiles - bi) { b -= ntiles - bi; ++bi; }
    const int bj = bi + b;

    __shared__ __align__(16) float sjp[TILE];  // p_j
    __shared__ __align__(16) float sjt[TILE];  // t_j

    const int tid = threadIdx.x;
    const int jb = bj * TILE;
    const int jlim = min(TILE, n - jb);

    #pragma unroll
    for (int k = tid; k < TILE; k += NTH) {
        if (k < jlim) {
            sjp[k] = p[jb + k];
            sjt[k] = t[jb + k];
        }
    }
    __syncthreads();

    const int ib = bi * TILE;
    unsigned int c0 = 0, c1 = 0, c2 = 0, c3 = 0;

    const bool full = (jlim == TILE) && (ib + TILE <= n);

    if (full && bi != bj) {
        // Full off-diagonal tile: all (i, j) valid. 2 rows/thread.
        const float p0 = p[ib + tid      ], t0 = t[ib + tid      ];
        const float p1 = p[ib + tid + NTH], t1 = t[ib + tid + NTH];

        const float4* JP = reinterpret_cast<const float4*>(sjp);
        const float4* JT = reinterpret_cast<const float4*>(sjt);

        #pragma unroll 4
        for (int k4 = 0; k4 < TILE / 4; ++k4) {
            const float4 jp = JP[k4];   // LDS.128 broadcast: 4 j's of p
            const float4 jt = JT[k4];   // LDS.128 broadcast: 4 j's of t
            acc_pair(c0, p0, t0, jp.x, jt.x);
            acc_pair(c1, p1, t1, jp.x, jt.x);
            acc_pair(c2, p0, t0, jp.y, jt.y);
            acc_pair(c3, p1, t1, jp.y, jt.y);
            acc_pair(c0, p0, t0, jp.z, jt.z);
            acc_pair(c1, p1, t1, jp.z, jt.z);
            acc_pair(c2, p0, t0, jp.w, jt.w);
            acc_pair(c3, p1, t1, jp.w, jt.w);
        }
    } else if (full) {
        // Diagonal tile: local j > local i.
        const float p0 = p[ib + tid      ], t0 = t[ib + tid      ];
        const float p1 = p[ib + tid + NTH], t1 = t[ib + tid + NTH];
        #pragma unroll 4
        for (int k = tid + 1; k < TILE; ++k)
            acc_pair(c0, p0, t0, sjp[k], sjt[k]);
        #pragma unroll 4
        for (int k = tid + NTH + 1; k < TILE; ++k)
            acc_pair(c1, p1, t1, sjp[k], sjt[k]);
    } else {
        // Partial tile (not hit for n=8192; kept for generality).
        #pragma unroll
        for (int r = 0; r < 2; ++r) {
            const int i = ib + tid + r * NTH;
            if (i < n) {
                const float pi = p[i], ti = t[i];
                for (int k = 0; k < jlim; ++k)
                    if (jb + k > i) acc_pair(c0, pi, ti, sjp[k], sjt[k]);
            }
        }
    }

    // Warp reduction: single REDUX.SUM.
    unsigned int cnt = __reduce_add_sync(0xFFFFFFFFu, (c0 + c1) + (c2 + c3));

    __shared__ unsigned int wsum[NTH / 32];
    if ((tid & 31) == 0) wsum[tid >> 5] = cnt;
    __syncthreads();

    if (tid == 0) {
        unsigned int total = 0;
        #pragma unroll
        for (int w = 0; w < NTH / 32; ++w) total += wsum[w];

        // One atomic: low 40 bits accumulate D, high bits count finished
        // blocks; the same atomic carries both, so no fence is needed.
        const unsigned long long pkt =
            (unsigned long long)total | (1ULL << 40);
        const unsigned long long old = atomicAdd(&g_cnt, pkt);
        if ((old >> 40) == (unsigned long long)(gridDim.x - 1)) {
            const unsigned long long D = (old + pkt) & ((1ULL << 40) - 1ULL);
            const double nn = (double)n;
            out[0] = (float)(4.0 * (double)D / (nn * (nn - 1.0)));
            atomicExch(&g_cnt, 0ULL);   // reset for next graph replay
        }
    }
}

extern "C" void kernel_launch(void* const* d_in, const int* in_sizes, int n_in,
                              void* d_out, int out_size)
{
    const float* predictions = (const float*)d_in[0];
    const float* true_labels = (const float*)d_in[1];
    float* out = (float*)d_out;
    const int n = in_sizes[0];

    const int ntiles = (n + TILE - 1) / TILE;
    const int nblocks = ntiles * (ntiles + 1) / 2;

    kt_kernel<<<nblocks, NTH>>>(predictions, true_labels, out, n);
}

// round 12
// speedup vs baseline: 2.0100x; 1.1955x over previous
#include <cuda_runtime.h>
#include <cstdint>

// Kendall's tau loss via discordant-pair count (no ties in random normals):
//   loss = 4*D / (n(n-1)),  D = #{i<j : sign(p_i-p_j) != sign(t_i-t_j)}
// R12: R8 inner math (fused FADD2+xor, dual-pipe accumulate) with the
// register cap removed (__launch_bounds__(NTH,1); every prior round was
// pinned at regs=30-32 -> MOV tax + no load batching) and the j-loop
// restructured to batch 4x LDS.128 (8 j's) ahead of 16 pair-ops.

#define TILE 256
#define NTH 128

__device__ unsigned long long g_cnt = 0;  // bits[0:40) count, bits[40:) block ctr

__device__ __forceinline__ unsigned long long pack2(float lo, float hi) {
    unsigned long long r;
    asm("mov.b64 %0, {%1, %2};" : "=l"(r) : "f"(lo), "f"(hi));
    return r;
}

// xor of the two fp32 halves of (a + nb), single asm block.
__device__ __forceinline__ unsigned int xor_word(unsigned long long a,
                                                 unsigned long long nb) {
    unsigned int r;
    asm("{\n\t"
        ".reg .b64 s;\n\t"
        ".reg .b32 lo, hi;\n\t"
        "add.rn.f32x2 s, %1, %2;\n\t"
        "mov.b64 {lo, hi}, s;\n\t"
        "xor.b32 %0, lo, hi;\n\t"
        "}" : "=r"(r) : "l"(a), "l"(nb));
    return r;
}

// alu-pipe accumulate: LEA.HI (c += bit31)
__device__ __forceinline__ void acc_alu(unsigned int& c, unsigned long long a,
                                        unsigned long long nb) {
    c += xor_word(a, nb) >> 31;
}
// fma-pipe accumulate: IMAD.HI.U32, multiplier ==2 but runtime-opaque
__device__ __forceinline__ void acc_fma(unsigned int& c, unsigned long long a,
                                        unsigned long long nb,
                                        unsigned int two) {
    unsigned int x = xor_word(a, nb);
    asm("mad.hi.u32 %0, %1, %2, %0;" : "+r"(c) : "r"(x), "r"(two));
}

__global__ __launch_bounds__(NTH, 1) void kt_kernel(
    const float* __restrict__ p, const float* __restrict__ t,
    float* __restrict__ out, int n)
{
    const int ntiles = (n + TILE - 1) / TILE;
    const unsigned int two = (unsigned int)blockDim.x >> 6;  // ==2, opaque

    // Linear block id -> upper-triangular (bi, bj), bj >= bi.
    int b = blockIdx.x;
    int bi = 0;
    while (b >= ntiles - bi) { b -= ntiles - bi; ++bi; }
    const int bj = bi + b;

    __shared__ __align__(16) float2 snb[TILE];  // (-p_j, -t_j)

    const int tid = threadIdx.x;
    const int jb = bj * TILE;
    const int jlim = min(TILE, n - jb);

    #pragma unroll
    for (int k = tid; k < TILE; k += NTH)
        if (k < jlim) snb[k] = make_float2(-p[jb + k], -t[jb + k]);
    __syncthreads();

    const int ib = bi * TILE;
    unsigned int c0 = 0, c1 = 0;

    const bool full = (jlim == TILE) && (ib + TILE <= n);

    if (full && bi != bj) {
        // Full off-diagonal tile: all (i, j) valid. 2 rows/thread.
        const unsigned long long a0 = pack2(p[ib + tid      ], t[ib + tid      ]);
        const unsigned long long a1 = pack2(p[ib + tid + NTH], t[ib + tid + NTH]);

        const ulonglong2* B2 = reinterpret_cast<const ulonglong2*>(snb);
        #pragma unroll
        for (int k8 = 0; k8 < TILE / 8; ++k8) {
            // Batch-load 8 j's (4x LDS.128) before any math -> MLP=4.
            const ulonglong2 b0 = B2[k8 * 4 + 0];
            const ulonglong2 b1 = B2[k8 * 4 + 1];
            const ulonglong2 b2 = B2[k8 * 4 + 2];
            const ulonglong2 b3 = B2[k8 * 4 + 3];

            acc_alu(c0, a0, b0.x);  acc_fma(c1, a1, b0.x, two);
            acc_alu(c0, a0, b0.y);  acc_fma(c1, a1, b0.y, two);
            acc_alu(c0, a0, b1.x);  acc_fma(c1, a1, b1.x, two);
            acc_alu(c0, a0, b1.y);  acc_fma(c1, a1, b1.y, two);
            acc_alu(c0, a0, b2.x);  acc_fma(c1, a1, b2.x, two);
            acc_alu(c0, a0, b2.y);  acc_fma(c1, a1, b2.y, two);
            acc_alu(c0, a0, b3.x);  acc_fma(c1, a1, b3.x, two);
            acc_alu(c0, a0, b3.y);  acc_fma(c1, a1, b3.y, two);
        }
    } else if (full) {
        // Diagonal tile: local j > local i.
        const unsigned long long* B =
            reinterpret_cast<const unsigned long long*>(snb);
        const unsigned long long a0 = pack2(p[ib + tid      ], t[ib + tid      ]);
        const unsigned long long a1 = pack2(p[ib + tid + NTH], t[ib + tid + NTH]);
        #pragma unroll 8
        for (int k = tid + 1; k < TILE; ++k) acc_alu(c0, a0, B[k]);
        #pragma unroll 8
        for (int k = tid + NTH + 1; k < TILE; ++k) acc_fma(c1, a1, B[k], two);
    } else {
        // Partial tile (not hit for n=8192; kept for generality).
        const unsigned long long* B =
            reinterpret_cast<const unsigned long long*>(snb);
        #pragma unroll
        for (int r = 0; r < 2; ++r) {
            const int i = ib + tid + r * NTH;
            if (i < n) {
                const unsigned long long a = pack2(p[i], t[i]);
                for (int k = 0; k < jlim; ++k)
                    if (jb + k > i) acc_alu(c0, a, B[k]);
            }
        }
    }

    // Warp reduction: single REDUX.SUM.
    unsigned int cnt = __reduce_add_sync(0xFFFFFFFFu, c0 + c1);

    __shared__ unsigned int wsum[NTH / 32];
    if ((tid & 31) == 0) wsum[tid >> 5] = cnt;
    __syncthreads();

    if (tid == 0) {
        unsigned int total = 0;
        #pragma unroll
        for (int w = 0; w < NTH / 32; ++w) total += wsum[w];

        // One atomic: low 40 bits accumulate D, high bits count finished
        // blocks; the same atomic carries both, so no fence is needed.
        const unsigned long long pkt =
            (unsigned long long)total | (1ULL << 40);
        const unsigned long long old = atomicAdd(&g_cnt, pkt);
        if ((old >> 40) == (unsigned long long)(gridDim.x - 1)) {
            const unsigned long long D = (old + pkt) & ((1ULL << 40) - 1ULL);
            const double nn = (double)n;
            out[0] = (float)(4.0 * (double)D / (nn * (nn - 1.0)));
            atomicExch(&g_cnt, 0ULL);   // reset for next graph replay
        }
    }
}

extern "C" void kernel_launch(void* const* d_in, const int* in_sizes, int n_in,
                              void* d_out, int out_size)
{
    const float* predictions = (const float*)d_in[0];
    const float* true_labels = (const float*)d_in[1];
    float* out = (float*)d_out;
    const int n = in_sizes[0];

    const int ntiles = (n + TILE - 1) / TILE;
    const int nblocks = ntiles * (ntiles + 1) / 2;

    kt_kernel<<<nblocks, NTH>>>(predictions, true_labels, out, n);
}